// round 1
// baseline (speedup 1.0000x reference)
#include <cuda_runtime.h>
#include <cuda_bf16.h>

#define CIN   64
#define COUT  64
#define KK    9
#define HH    128
#define WW    128
#define HW    (HH*WW)
#define NBATCH 4
#define THREADS 256

// weight reordered in smem as wk[(c*9+k)*64 + o]
#define SMEM_BYTES (CIN*KK*COUT*4)

__global__ __launch_bounds__(THREADS, 1)
void dcnv2_kernel(const float* __restrict__ x,
                  const float* __restrict__ offset,
                  const float* __restrict__ mask,
                  const float* __restrict__ weight,
                  const float* __restrict__ bias,
                  float* __restrict__ out) {
    extern __shared__ float wk[];  // [576][64]

    const int tid = threadIdx.x;

    // Cooperative weight stage + reorder: wk[ck*64+o] = weight[o*576+ck]
    for (int i = tid; i < CIN * KK * COUT; i += THREADS) {
        int o  = i & 63;
        int ck = i >> 6;
        wk[i] = weight[o * (CIN * KK) + ck];
    }
    __syncthreads();

    const int pix = blockIdx.x * THREADS + tid;   // < N*H*W = 65536
    const int n   = pix >> 14;
    const int rem = pix & 16383;
    const int ho  = rem >> 7;
    const int wo  = rem & 127;

    float acc[COUT];
    #pragma unroll
    for (int o = 0; o < COUT; o++) acc[o] = bias[o];

    const float* xn   = x + n * CIN * HW;
    const float* offp = offset + ((size_t)(n * 18) * HH + ho) * WW + wo;
    const float* mp   = mask   + ((size_t)(n *  9) * HH + ho) * WW + wo;

    #pragma unroll
    for (int k = 0; k < KK; k++) {
        const int ky = k / 3, kx = k % 3;
        const float offy = offp[(2 * k + 0) * HW];
        const float offx = offp[(2 * k + 1) * HW];
        const float m    = mp[k * HW];

        const float py = (float)(ho - 1 + ky) + offy;
        const float px = (float)(wo - 1 + kx) + offx;
        const float fy = floorf(py), fx = floorf(px);
        const float ly = py - fy,   lx = px - fx;
        const int y0 = (int)fy, x0 = (int)fx;
        const int y1 = y0 + 1,  x1 = x0 + 1;

        const bool vy0 = (y0 >= 0) & (y0 < HH);
        const bool vy1 = (y1 >= 0) & (y1 < HH);
        const bool vx0 = (x0 >= 0) & (x0 < WW);
        const bool vx1 = (x1 >= 0) & (x1 < WW);

        float w00 = (1.f - ly) * (1.f - lx) * m; if (!(vy0 && vx0)) w00 = 0.f;
        float w01 = (1.f - ly) * lx         * m; if (!(vy0 && vx1)) w01 = 0.f;
        float w10 = ly         * (1.f - lx) * m; if (!(vy1 && vx0)) w10 = 0.f;
        float w11 = ly         * lx         * m; if (!(vy1 && vx1)) w11 = 0.f;

        const int cy0 = min(max(y0, 0), HH - 1);
        const int cy1 = min(max(y1, 0), HH - 1);
        const int cx0 = min(max(x0, 0), WW - 1);
        const int cx1 = min(max(x1, 0), WW - 1);
        const int i00 = cy0 * WW + cx0;
        const int i01 = cy0 * WW + cx1;
        const int i10 = cy1 * WW + cx0;
        const int i11 = cy1 * WW + cx1;

        #pragma unroll 2
        for (int c = 0; c < CIN; c++) {
            const float* xc = xn + c * HW;
            const float v00 = __ldg(xc + i00);
            const float v01 = __ldg(xc + i01);
            const float v10 = __ldg(xc + i10);
            const float v11 = __ldg(xc + i11);
            const float val = w00 * v00 + w01 * v01 + w10 * v10 + w11 * v11;

            const float4* w4 = (const float4*)(wk + (c * KK + k) * COUT);
            #pragma unroll
            for (int o4 = 0; o4 < COUT / 4; o4++) {
                const float4 wv = w4[o4];
                acc[4 * o4 + 0] += val * wv.x;
                acc[4 * o4 + 1] += val * wv.y;
                acc[4 * o4 + 2] += val * wv.z;
                acc[4 * o4 + 3] += val * wv.w;
            }
        }
    }

    float* op = out + (size_t)n * COUT * HW + ho * WW + wo;
    #pragma unroll
    for (int o = 0; o < COUT; o++) op[o * HW] = acc[o];
}

extern "C" void kernel_launch(void* const* d_in, const int* in_sizes, int n_in,
                              void* d_out, int out_size) {
    const float* x      = (const float*)d_in[0];
    const float* offset = (const float*)d_in[1];
    const float* mask   = (const float*)d_in[2];
    const float* weight = (const float*)d_in[3];
    const float* bias   = (const float*)d_in[4];
    float* out = (float*)d_out;

    cudaFuncSetAttribute(dcnv2_kernel,
                         cudaFuncAttributeMaxDynamicSharedMemorySize, SMEM_BYTES);

    const int total = NBATCH * HH * WW;           // 65536 pixels
    const int blocks = total / THREADS;           // 256
    dcnv2_kernel<<<blocks, THREADS, SMEM_BYTES>>>(x, offset, mask, weight, bias, out);
}

// round 2
// speedup vs baseline: 1.1065x; 1.1065x over previous
#include <cuda_runtime.h>
#include <cuda_bf16.h>

#define CIN   64
#define COUT  64
#define KK    9
#define HH    128
#define WW    128
#define HW    (HH*WW)
#define NBATCH 4
#define THREADS 256
#define CHALF 32                    // couts per CTA
#define SMEM_BYTES (CIN*KK*CHALF*4) // 73728 B

typedef unsigned long long u64t;

__device__ __forceinline__ u64t fma2(u64t a, u64t b, u64t c) {
    u64t d;
    asm("fma.rn.f32x2 %0, %1, %2, %3;" : "=l"(d) : "l"(a), "l"(b), "l"(c));
    return d;
}
__device__ __forceinline__ u64t pack2(float lo, float hi) {
    u64t d;
    asm("mov.b64 %0, {%1, %2};" : "=l"(d) : "f"(lo), "f"(hi));
    return d;
}
__device__ __forceinline__ void unpack2(u64t v, float& lo, float& hi) {
    asm("mov.b64 {%0, %1}, %2;" : "=f"(lo), "=f"(hi) : "l"(v));
}

struct Corner {
    int i00, i01, i10, i11;
    float w00, w01, w10, w11;
};

__device__ __forceinline__ Corner make_corner(int ho, int wo, int ky, int kx,
                                              float offy, float offx, float m) {
    Corner r;
    const float py = (float)(ho - 1 + ky) + offy;
    const float px = (float)(wo - 1 + kx) + offx;
    const float fy = floorf(py), fx = floorf(px);
    const float ly = py - fy, lx = px - fx;
    const int y0 = (int)fy, x0 = (int)fx;
    const int y1 = y0 + 1,  x1 = x0 + 1;
    const bool vy0 = (y0 >= 0) & (y0 < HH);
    const bool vy1 = (y1 >= 0) & (y1 < HH);
    const bool vx0 = (x0 >= 0) & (x0 < WW);
    const bool vx1 = (x1 >= 0) & (x1 < WW);
    r.w00 = (vy0 && vx0) ? (1.f - ly) * (1.f - lx) * m : 0.f;
    r.w01 = (vy0 && vx1) ? (1.f - ly) * lx         * m : 0.f;
    r.w10 = (vy1 && vx0) ? ly         * (1.f - lx) * m : 0.f;
    r.w11 = (vy1 && vx1) ? ly         * lx         * m : 0.f;
    const int cy0 = min(max(y0, 0), HH - 1);
    const int cy1 = min(max(y1, 0), HH - 1);
    const int cx0 = min(max(x0, 0), WW - 1);
    const int cx1 = min(max(x1, 0), WW - 1);
    r.i00 = cy0 * WW + cx0;
    r.i01 = cy0 * WW + cx1;
    r.i10 = cy1 * WW + cx0;
    r.i11 = cy1 * WW + cx1;
    return r;
}

__global__ __launch_bounds__(THREADS, 2)
void dcnv2_kernel(const float* __restrict__ x,
                  const float* __restrict__ offset,
                  const float* __restrict__ mask,
                  const float* __restrict__ weight,
                  const float* __restrict__ bias,
                  float* __restrict__ out) {
    extern __shared__ float wk[];  // [576][32] for this CTA's cout half

    const int tid  = threadIdx.x;
    const int half = blockIdx.y;          // 0 or 1
    const int obase = half * CHALF;

    // Stage + reorder weights for our 32 couts: wk[ck*32 + o] = weight[(obase+o)*576 + ck]
    for (int i = tid; i < CIN * KK * CHALF; i += THREADS) {
        const int o  = i & (CHALF - 1);
        const int ck = i >> 5;
        wk[i] = weight[(obase + o) * (CIN * KK) + ck];
    }
    __syncthreads();

    // Two pixels per thread: p0 = base+tid, p1 = p0+256 (same batch n)
    const int pix0 = blockIdx.x * (2 * THREADS) + tid;
    const int pix1 = pix0 + THREADS;
    const int n    = pix0 >> 14;
    const int rem0 = pix0 & 16383, rem1 = pix1 & 16383;
    const int ho0 = rem0 >> 7, wo0 = rem0 & 127;
    const int ho1 = rem1 >> 7, wo1 = rem1 & 127;

    u64t acc0[CHALF / 2], acc1[CHALF / 2];
    #pragma unroll
    for (int j = 0; j < CHALF / 2; j++) {
        const float b0 = bias[obase + 2 * j];
        const float b1 = bias[obase + 2 * j + 1];
        acc0[j] = pack2(b0, b1);
        acc1[j] = pack2(b0, b1);
    }

    const float* xn    = x + n * CIN * HW;
    const float* offp0 = offset + ((size_t)(n * 18) * HH + ho0) * WW + wo0;
    const float* offp1 = offset + ((size_t)(n * 18) * HH + ho1) * WW + wo1;
    const float* mp0   = mask   + ((size_t)(n *  9) * HH + ho0) * WW + wo0;
    const float* mp1   = mask   + ((size_t)(n *  9) * HH + ho1) * WW + wo1;

    #pragma unroll
    for (int k = 0; k < KK; k++) {
        const int ky = k / 3, kx = k % 3;
        const Corner ca = make_corner(ho0, wo0, ky, kx,
                                      offp0[(2 * k) * HW], offp0[(2 * k + 1) * HW],
                                      mp0[k * HW]);
        const Corner cb = make_corner(ho1, wo1, ky, kx,
                                      offp1[(2 * k) * HW], offp1[(2 * k + 1) * HW],
                                      mp1[k * HW]);

        #pragma unroll 4
        for (int c = 0; c < CIN; c++) {
            const float* xc = xn + c * HW;
            const float a00 = __ldg(xc + ca.i00);
            const float a01 = __ldg(xc + ca.i01);
            const float a10 = __ldg(xc + ca.i10);
            const float a11 = __ldg(xc + ca.i11);
            const float b00 = __ldg(xc + cb.i00);
            const float b01 = __ldg(xc + cb.i01);
            const float b10 = __ldg(xc + cb.i10);
            const float b11 = __ldg(xc + cb.i11);

            float va = ca.w00 * a00;
            va = fmaf(ca.w01, a01, va);
            va = fmaf(ca.w10, a10, va);
            va = fmaf(ca.w11, a11, va);
            float vb = cb.w00 * b00;
            vb = fmaf(cb.w01, b01, vb);
            vb = fmaf(cb.w10, b10, vb);
            vb = fmaf(cb.w11, b11, vb);

            const u64t va2 = pack2(va, va);
            const u64t vb2 = pack2(vb, vb);

            const ulonglong2* w2 = (const ulonglong2*)(wk + (c * KK + k) * CHALF);
            #pragma unroll
            for (int j = 0; j < CHALF / 4; j++) {   // 8 iterations, LDS.128 each
                const ulonglong2 wv = w2[j];
                acc0[2 * j]     = fma2(va2, wv.x, acc0[2 * j]);
                acc0[2 * j + 1] = fma2(va2, wv.y, acc0[2 * j + 1]);
                acc1[2 * j]     = fma2(vb2, wv.x, acc1[2 * j]);
                acc1[2 * j + 1] = fma2(vb2, wv.y, acc1[2 * j + 1]);
            }
        }
    }

    float* op0 = out + ((size_t)n * COUT + obase) * HW + ho0 * WW + wo0;
    float* op1 = out + ((size_t)n * COUT + obase) * HW + ho1 * WW + wo1;
    #pragma unroll
    for (int j = 0; j < CHALF / 2; j++) {
        float lo, hi;
        unpack2(acc0[j], lo, hi);
        op0[(2 * j) * HW] = lo;
        op0[(2 * j + 1) * HW] = hi;
        unpack2(acc1[j], lo, hi);
        op1[(2 * j) * HW] = lo;
        op1[(2 * j + 1) * HW] = hi;
    }
}

extern "C" void kernel_launch(void* const* d_in, const int* in_sizes, int n_in,
                              void* d_out, int out_size) {
    const float* x      = (const float*)d_in[0];
    const float* offset = (const float*)d_in[1];
    const float* mask   = (const float*)d_in[2];
    const float* weight = (const float*)d_in[3];
    const float* bias   = (const float*)d_in[4];
    float* out = (float*)d_out;

    cudaFuncSetAttribute(dcnv2_kernel,
                         cudaFuncAttributeMaxDynamicSharedMemorySize, SMEM_BYTES);

    const int total = NBATCH * HH * WW;                  // 65536 pixels
    dim3 grid(total / (2 * THREADS), 2);                 // 128 pixel-blocks x 2 cout halves
    dcnv2_kernel<<<grid, THREADS, SMEM_BYTES>>>(x, offset, mask, weight, bias, out);
}